// round 3
// baseline (speedup 1.0000x reference)
#include <cuda_runtime.h>
#include <math.h>

#define Ldim 128
#define Ddim 512
#define Mdim 2048
#define NTAIL 127

__device__ float g_A[Ldim*Ddim];
__device__ float g_Bm[Ldim*Ddim];
__device__ float g_T[Ldim*Mdim];
__device__ float g_U[Ldim*Mdim];
__device__ float g_G[5][Ldim*Ddim];
__device__ float g_S[Ddim*Ddim];
__device__ float g_P0[Ddim*Ddim];
__device__ float g_P1[Ddim*Ddim];
__device__ float g_Delta[Ldim*Ldim];
__device__ float g_DtD[Ldim*Ldim];
__device__ float g_Q0[Ldim*Ldim];
__device__ float g_Q1[Ldim*Ldim];
__device__ float g_ytail[NTAIL];
__device__ float g_red[4];
__device__ float g_scal[4];   // [0]=maxeig(xxT) [1]=maxeig(DtD) [2]=tau [3]=thr
__device__ int   g_done;

// ---------- init / constants ----------
__global__ void k_init(const float* __restrict__ mask, const float* __restrict__ py,
                       const float* __restrict__ y0) {
    int idx = blockIdx.x * blockDim.x + threadIdx.x;
    if (idx < Ldim*Ddim) { g_A[idx] = 0.f; g_Bm[idx] = 0.f; }
    if (idx < Ldim*Mdim) { g_U[idx] = -mask[idx] * py[idx]; }
    if (idx < NTAIL)     { g_ytail[idx] = y0[Mdim + idx]; }
    if (idx == 0)        { g_done = 0; }
}

__global__ void k_delta() {
    int idx = blockIdx.x * blockDim.x + threadIdx.x;
    if (idx < Ldim*Ldim) {
        int p = idx >> 7, c = idx & 127;
        float v = (c == p) ? 1.f : ((c == p-1) ? -2.f : ((c == p-2) ? 1.f : 0.f));
        if (p == 0 && c == 0) v = 0.f;
        if (p == 1 && c == 0) v = -1.f;
        g_Delta[idx] = v;
    }
}

__global__ void k_dtd() {
    int idx = blockIdx.x * blockDim.x + threadIdx.x;
    if (idx < Ldim*Ldim) {
        int i = idx >> 7, j = idx & 127;
        float s = 0.f;
        for (int p = 0; p < 128; p++) s += g_Delta[p*128 + i] * g_Delta[p*128 + j];
        g_DtD[idx] = s;
    }
}

// ---------- generic NT GEMM: C[i,j] = sum_k A[i*K+k]*B[j*K+k], C is n x n ----------
__global__ void gemm_nt(const float* __restrict__ A, const float* __restrict__ B,
                        float* __restrict__ C, int n, int K) {
    __shared__ float As[32][33];
    __shared__ float Bs[32][33];
    int i0 = blockIdx.x * 32, j0 = blockIdx.y * 32;
    int tid = threadIdx.x;
    int tr = tid >> 5, tc = tid & 31;
    int ti = tid >> 4, tj = tid & 15;
    float a00=0.f, a01=0.f, a10=0.f, a11=0.f;
    for (int k0 = 0; k0 < K; k0 += 32) {
        #pragma unroll
        for (int r = 0; r < 4; r++) {
            As[tc][tr + 8*r] = A[(size_t)(i0 + tr + 8*r) * K + k0 + tc];
            Bs[tc][tr + 8*r] = B[(size_t)(j0 + tr + 8*r) * K + k0 + tc];
        }
        __syncthreads();
        #pragma unroll
        for (int kk = 0; kk < 32; kk++) {
            float av0 = As[kk][2*ti], av1 = As[kk][2*ti+1];
            float bv0 = Bs[kk][2*tj], bv1 = Bs[kk][2*tj+1];
            a00 += av0*bv0; a01 += av0*bv1; a10 += av1*bv0; a11 += av1*bv1;
        }
        __syncthreads();
    }
    int i = i0 + 2*ti, j = j0 + 2*tj;
    C[(size_t)i*n + j]     = a00; C[(size_t)i*n + j+1]     = a01;
    C[(size_t)(i+1)*n + j] = a10; C[(size_t)(i+1)*n + j+1] = a11;
}

// ---------- trace / normalize ----------
__global__ void k_trace(const float* __restrict__ m, int n) {
    __shared__ float sh[512];
    int t = threadIdx.x;
    sh[t] = (t < n) ? m[t*n + t] : 0.f;
    __syncthreads();
    for (int off = 256; off > 0; off >>= 1) {
        if (t < off) sh[t] += sh[t + off];
        __syncthreads();
    }
    if (t == 0) g_red[0] = sh[0];
}

__global__ void k_normmat(const float* __restrict__ src, float* __restrict__ dst, int nn) {
    float inv = 1.f / g_red[0];
    int idx = blockIdx.x * blockDim.x + threadIdx.x;
    if (idx < nn) dst[idx] = src[idx] * inv;
}

// ---------- Rayleigh: v = P*r, lambda = (v^T S v)/(v^T v) ----------
__global__ void k_rayleigh(const float* __restrict__ P, const float* __restrict__ S,
                           int n, int slot) {
    __shared__ float v[512];
    __shared__ float r1[512], r2[512];
    int t = threadIdx.x;
    float s = 0.f;
    for (int j = 0; j < n; j++) s += P[t*n + j] * (sinf(0.7331f * j + 0.1234f) + 1.5f);
    v[t] = s;
    __syncthreads();
    float w = 0.f;
    for (int j = 0; j < n; j++) w += S[t*n + j] * v[j];
    r1[t] = v[t] * w;
    r2[t] = v[t] * v[t];
    __syncthreads();
    for (int off = n >> 1; off > 0; off >>= 1) {
        if (t < off) { r1[t] += r1[t+off]; r2[t] += r2[t+off]; }
        __syncthreads();
    }
    if (t == 0) g_scal[slot] = r1[0] / r2[0];
}

__global__ void k_scalars() {
    float tau = 1.0f / (2.0f * (g_scal[0] + 0.1f * g_scal[1]));
    float lam2 = (tau * 0.1f > 0.1f) ? (0.1f / tau) : 0.1f;
    g_scal[2] = tau;
    g_scal[3] = tau * lam2;
}

// ---------- gradient: z in 0..3 -> U-chunk @ x^T (split-K), z==4 -> 0.1*DtD@A ----------
__global__ void gemm_grad(const float* __restrict__ x) {
    if (g_done) return;
    __shared__ __align__(16) float Us[32][33];
    __shared__ __align__(16) float Xs[32][68];
    int z = blockIdx.z;
    int i0 = blockIdx.x * 32, j0 = blockIdx.y * 64;
    int tid = threadIdx.x;
    int ti = tid >> 4, tj = tid & 15;
    int tr = tid >> 5, tc = tid & 31;
    int rr = tid >> 6, cc = tid & 63;
    float acc[2][4] = {};
    int nk = (z < 4) ? 16 : 4;
    for (int kt = 0; kt < nk; kt++) {
        if (z < 4) {
            int m0 = z * 512 + kt * 32;
            #pragma unroll
            for (int r = 0; r < 4; r++)
                Us[tc][tr + 8*r] = g_U[(size_t)(i0 + tr + 8*r) * Mdim + m0 + tc];
            #pragma unroll
            for (int r = 0; r < 8; r++)
                Xs[tc][tr + 8*r] = x[(size_t)(j0 + tr + 8*r) * Mdim + m0 + tc];
        } else {
            int p0 = kt * 32;
            #pragma unroll
            for (int r = 0; r < 4; r++)
                Us[tc][tr + 8*r] = g_DtD[(i0 + tr + 8*r) * Ldim + p0 + tc];
            #pragma unroll
            for (int r = 0; r < 8; r++)
                Xs[rr + 4*r][cc] = g_A[(p0 + rr + 4*r) * Ddim + j0 + cc];
        }
        __syncthreads();
        #pragma unroll
        for (int kk = 0; kk < 32; kk++) {
            float av0 = Us[kk][2*ti], av1 = Us[kk][2*ti+1];
            float4 b = *reinterpret_cast<const float4*>(&Xs[kk][4*tj]);
            acc[0][0] += av0*b.x; acc[0][1] += av0*b.y; acc[0][2] += av0*b.z; acc[0][3] += av0*b.w;
            acc[1][0] += av1*b.x; acc[1][1] += av1*b.y; acc[1][2] += av1*b.z; acc[1][3] += av1*b.w;
        }
        __syncthreads();
    }
    float sc = (z == 4) ? 0.1f : 1.0f;
    int i = i0 + 2*ti, j = j0 + 4*tj;
    float* outp = &g_G[z][0];
    #pragma unroll
    for (int r = 0; r < 2; r++)
        #pragma unroll
        for (int c = 0; c < 4; c++)
            outp[(i + r) * Ddim + j + c] = acc[r][c] * sc;
}

// ---------- prox + momentum ----------
__global__ void k_update(float coeff) {
    if (g_done) return;
    float tau = g_scal[2], thr = g_scal[3];
    int idx = blockIdx.x * blockDim.x + threadIdx.x;   // exactly L*D threads
    float g = g_G[0][idx] + g_G[1][idx] + g_G[2][idx] + g_G[3][idx] + g_G[4][idx];
    float aold = g_A[idx], b = g_Bm[idx];
    float zv = b - tau * g;
    float az = fabsf(zv) - thr;
    float anew = (az > 0.f) ? copysignf(az, zv) : 0.f;
    g_A[idx]  = anew;
    g_Bm[idx] = aold + coeff * (anew - aold);
}

// ---------- forward: T = A@x, U = mask*(T - py) ----------
__global__ void gemm_fwd(const float* __restrict__ x, const float* __restrict__ py,
                         const float* __restrict__ mask) {
    if (g_done) return;
    __shared__ __align__(16) float As[32][33];
    __shared__ __align__(16) float Xs[32][68];
    int i0 = blockIdx.x * 32, m0 = blockIdx.y * 64;
    int tid = threadIdx.x;
    int ti = tid >> 4, tj = tid & 15;
    int tr = tid >> 5, tc = tid & 31;
    int rr = tid >> 6, cc = tid & 63;
    float acc[2][4] = {};
    for (int k0 = 0; k0 < Ddim; k0 += 32) {
        #pragma unroll
        for (int r = 0; r < 4; r++)
            As[tc][tr + 8*r] = g_A[(i0 + tr + 8*r) * Ddim + k0 + tc];
        #pragma unroll
        for (int r = 0; r < 8; r++)
            Xs[rr + 4*r][cc] = x[(size_t)(k0 + rr + 4*r) * Mdim + m0 + cc];
        __syncthreads();
        #pragma unroll
        for (int kk = 0; kk < 32; kk++) {
            float av0 = As[kk][2*ti], av1 = As[kk][2*ti+1];
            float4 b = *reinterpret_cast<const float4*>(&Xs[kk][4*tj]);
            acc[0][0] += av0*b.x; acc[0][1] += av0*b.y; acc[0][2] += av0*b.z; acc[0][3] += av0*b.w;
            acc[1][0] += av1*b.x; acc[1][1] += av1*b.y; acc[1][2] += av1*b.z; acc[1][3] += av1*b.w;
        }
        __syncthreads();
    }
    #pragma unroll
    for (int r = 0; r < 2; r++) {
        int i = i0 + 2*ti + r;
        #pragma unroll
        for (int c = 0; c < 4; c++) {
            int m = m0 + 4*tj + c;
            size_t o = (size_t)i * Mdim + m;
            float t = acc[r][c];
            g_T[o] = t;
            g_U[o] = mask[o] * (t - py[o]);
        }
    }
}

// ---------- convergence on Hankel tail ----------
__global__ void k_conv() {
    if (g_done) return;
    __shared__ float ax[128], r1[128], r2[128];
    int t = threadIdx.x;  // 128 threads
    float s = 0.f;
    if (t < NTAIL) {
        for (int i = t + 1; i < Ldim; i++) s += g_T[i * Mdim + (Mdim + t - i)];
        s /= (float)(NTAIL - t);
    }
    float y = (t < NTAIL) ? g_ytail[t] : 0.f;
    float d = (t < NTAIL) ? (y - s) : 0.f;
    ax[t] = s; r1[t] = d * d; r2[t] = y * y;
    __syncthreads();
    for (int off = 64; off > 0; off >>= 1) {
        if (t < off) { r1[t] += r1[t+off]; r2[t] += r2[t+off]; }
        __syncthreads();
    }
    if (t == 0 && sqrtf(r1[0] / r2[0]) <= 1e-5f) g_done = 1;
    if (t < NTAIL) g_ytail[t] = ax[t];
}

// ---------- output: (A@x, A) ----------
__global__ void k_output(float* __restrict__ out, int out_size) {
    int idx = blockIdx.x * blockDim.x + threadIdx.x;
    if (idx >= out_size) return;
    if (idx < Ldim*Mdim) out[idx] = g_T[idx];
    else if (idx < Ldim*Mdim + Ldim*Ddim) out[idx] = g_A[idx - Ldim*Mdim];
}

extern "C" void kernel_launch(void* const* d_in, const int* in_sizes, int n_in,
                              void* d_out, int out_size) {
    const float* x    = (const float*)d_in[0];
    const float* py   = (const float*)d_in[1];
    const float* mask = (const float*)d_in[2];
    const float* y0   = (const float*)d_in[3];
    float* outp = (float*)d_out;

    void *pS, *pP0, *pP1, *pDtD, *pQ0, *pQ1;
    cudaGetSymbolAddress(&pS,   g_S);
    cudaGetSymbolAddress(&pP0,  g_P0);
    cudaGetSymbolAddress(&pP1,  g_P1);
    cudaGetSymbolAddress(&pDtD, g_DtD);
    cudaGetSymbolAddress(&pQ0,  g_Q0);
    cudaGetSymbolAddress(&pQ1,  g_Q1);

    // init + constants
    k_init<<<(Ldim*Mdim + 255)/256, 256>>>(mask, py, y0);
    k_delta<<<(Ldim*Ldim + 255)/256, 256>>>();
    k_dtd<<<(Ldim*Ldim + 255)/256, 256>>>();

    // maxeig(x x^T) via 10 squarings + Rayleigh
    gemm_nt<<<dim3(16,16), 256>>>(x, x, (float*)pS, Ddim, Mdim);
    k_trace<<<1, 512>>>((const float*)pS, Ddim);
    k_normmat<<<(Ddim*Ddim + 255)/256, 256>>>((const float*)pS, (float*)pP0, Ddim*Ddim);
    for (int i = 0; i < 10; i++) {
        gemm_nt<<<dim3(16,16), 256>>>((const float*)pP0, (const float*)pP0, (float*)pP1, Ddim, Ddim);
        k_trace<<<1, 512>>>((const float*)pP1, Ddim);
        k_normmat<<<(Ddim*Ddim + 255)/256, 256>>>((const float*)pP1, (float*)pP0, Ddim*Ddim);
    }
    k_rayleigh<<<1, Ddim>>>((const float*)pP0, (const float*)pS, Ddim, 0);

    // maxeig(DtD) via 17 squarings + Rayleigh
    k_trace<<<1, 512>>>((const float*)pDtD, Ldim);
    k_normmat<<<(Ldim*Ldim + 255)/256, 256>>>((const float*)pDtD, (float*)pQ0, Ldim*Ldim);
    for (int i = 0; i < 17; i++) {
        gemm_nt<<<dim3(4,4), 256>>>((const float*)pQ0, (const float*)pQ0, (float*)pQ1, Ldim, Ldim);
        k_trace<<<1, 512>>>((const float*)pQ1, Ldim);
        k_normmat<<<(Ldim*Ldim + 255)/256, 256>>>((const float*)pQ1, (float*)pQ0, Ldim*Ldim);
    }
    k_rayleigh<<<1, Ldim>>>((const float*)pQ0, (const float*)pDtD, Ldim, 1);

    k_scalars<<<1, 1>>>();

    // FISTA loop: 200 fixed iterations, device-side early-exit flag
    float a = 1.0f;
    for (int it = 0; it < 200; it++) {
        float anew = (1.0f + sqrtf(1.0f + 4.0f * a * a)) * 0.5f;
        float coeff = (a - 1.0f) / anew;
        a = anew;
        gemm_grad<<<dim3(Ldim/32, Ddim/64, 5), 256>>>(x);
        k_update<<<(Ldim*Ddim)/256, 256>>>(coeff);
        gemm_fwd<<<dim3(Ldim/32, Mdim/64), 256>>>(x, py, mask);
        k_conv<<<1, 128>>>();
    }

    k_output<<<(out_size + 255)/256, 256>>>(outp, out_size);
}

// round 4
// speedup vs baseline: 1.4377x; 1.4377x over previous
#include <cuda_runtime.h>
#include <math.h>

#define Ldim 128
#define Ddim 512
#define Mdim 2048
#define NTAIL 127

__device__ float g_A[Ldim*Ddim];
__device__ float g_Bm[Ldim*Ddim];
__device__ float g_T[Ldim*Mdim];
__device__ float g_U[Ldim*Mdim];
__device__ float g_G[5][Ldim*Ddim];
__device__ float g_S[Ddim*Ddim];
__device__ float g_P0[Ddim*Ddim];
__device__ float g_P1[Ddim*Ddim];
__device__ float g_Delta[Ldim*Ldim];
__device__ float g_DtD[Ldim*Ldim];
__device__ float g_Q0[Ldim*Ldim];
__device__ float g_Q1[Ldim*Ldim];
__device__ float g_ytail[NTAIL];
__device__ float g_red[4];
__device__ float g_scal[4];   // [0]=maxeig(xxT) [1]=maxeig(DtD) [2]=tau [3]=thr
__device__ int   g_done;

// ---------- init / constants ----------
__global__ void k_init(const float* __restrict__ mask, const float* __restrict__ py,
                       const float* __restrict__ y0) {
    int idx = blockIdx.x * blockDim.x + threadIdx.x;
    if (idx < Ldim*Ddim) { g_A[idx] = 0.f; g_Bm[idx] = 0.f; }
    if (idx < Ldim*Mdim) { g_U[idx] = -mask[idx] * py[idx]; }
    if (idx < NTAIL)     { g_ytail[idx] = y0[Mdim + idx]; }
    if (idx == 0)        { g_done = 0; }
}

__global__ void k_delta() {
    int idx = blockIdx.x * blockDim.x + threadIdx.x;
    if (idx < Ldim*Ldim) {
        int p = idx >> 7, c = idx & 127;
        float v = (c == p) ? 1.f : ((c == p-1) ? -2.f : ((c == p-2) ? 1.f : 0.f));
        if (p == 0 && c == 0) v = 0.f;
        if (p == 1 && c == 0) v = -1.f;
        g_Delta[idx] = v;
    }
}

__global__ void k_dtd() {
    int idx = blockIdx.x * blockDim.x + threadIdx.x;
    if (idx < Ldim*Ldim) {
        int i = idx >> 7, j = idx & 127;
        float s = 0.f;
        for (int p = 0; p < 128; p++) s += g_Delta[p*128 + i] * g_Delta[p*128 + j];
        g_DtD[idx] = s;
    }
}

// ---------- generic NT GEMM (precompute only) ----------
__global__ void gemm_nt(const float* __restrict__ A, const float* __restrict__ B,
                        float* __restrict__ C, int n, int K) {
    __shared__ float As[32][33];
    __shared__ float Bs[32][33];
    int i0 = blockIdx.x * 32, j0 = blockIdx.y * 32;
    int tid = threadIdx.x;
    int tr = tid >> 5, tc = tid & 31;
    int ti = tid >> 4, tj = tid & 15;
    float a00=0.f, a01=0.f, a10=0.f, a11=0.f;
    for (int k0 = 0; k0 < K; k0 += 32) {
        #pragma unroll
        for (int r = 0; r < 4; r++) {
            As[tc][tr + 8*r] = A[(size_t)(i0 + tr + 8*r) * K + k0 + tc];
            Bs[tc][tr + 8*r] = B[(size_t)(j0 + tr + 8*r) * K + k0 + tc];
        }
        __syncthreads();
        #pragma unroll
        for (int kk = 0; kk < 32; kk++) {
            float av0 = As[kk][2*ti], av1 = As[kk][2*ti+1];
            float bv0 = Bs[kk][2*tj], bv1 = Bs[kk][2*tj+1];
            a00 += av0*bv0; a01 += av0*bv1; a10 += av1*bv0; a11 += av1*bv1;
        }
        __syncthreads();
    }
    int i = i0 + 2*ti, j = j0 + 2*tj;
    C[(size_t)i*n + j]     = a00; C[(size_t)i*n + j+1]     = a01;
    C[(size_t)(i+1)*n + j] = a10; C[(size_t)(i+1)*n + j+1] = a11;
}

// ---------- trace / normalize ----------
__global__ void k_trace(const float* __restrict__ m, int n) {
    __shared__ float sh[512];
    int t = threadIdx.x;
    sh[t] = (t < n) ? m[t*n + t] : 0.f;
    __syncthreads();
    for (int off = 256; off > 0; off >>= 1) {
        if (t < off) sh[t] += sh[t + off];
        __syncthreads();
    }
    if (t == 0) g_red[0] = sh[0];
}

__global__ void k_normmat(const float* __restrict__ src, float* __restrict__ dst, int nn) {
    float inv = 1.f / g_red[0];
    int idx = blockIdx.x * blockDim.x + threadIdx.x;
    if (idx < nn) dst[idx] = src[idx] * inv;
}

// ---------- Rayleigh ----------
__global__ void k_rayleigh(const float* __restrict__ P, const float* __restrict__ S,
                           int n, int slot) {
    __shared__ float v[512];
    __shared__ float r1[512], r2[512];
    int t = threadIdx.x;
    float s = 0.f;
    for (int j = 0; j < n; j++) s += P[t*n + j] * (sinf(0.7331f * j + 0.1234f) + 1.5f);
    v[t] = s;
    __syncthreads();
    float w = 0.f;
    for (int j = 0; j < n; j++) w += S[t*n + j] * v[j];
    r1[t] = v[t] * w;
    r2[t] = v[t] * v[t];
    __syncthreads();
    for (int off = n >> 1; off > 0; off >>= 1) {
        if (t < off) { r1[t] += r1[t+off]; r2[t] += r2[t+off]; }
        __syncthreads();
    }
    if (t == 0) g_scal[slot] = r1[0] / r2[0];
}

__global__ void k_scalars() {
    float tau = 1.0f / (2.0f * (g_scal[0] + 0.1f * g_scal[1]));
    float lam2 = (tau * 0.1f > 0.1f) ? (0.1f / tau) : 0.1f;
    g_scal[2] = tau;
    g_scal[3] = tau * lam2;
}

// ---------- gradient: z 0..3 -> U-chunk @ x^T (split-K), z==4 -> 0.1*DtD@A ----------
// Pipelined: double-buffered smem + register-prefetched inner loop.
__global__ void __launch_bounds__(256) gemm_grad(const float* __restrict__ x) {
    if (g_done) return;
    __shared__ __align__(16) float Us[2][32][34];
    __shared__ __align__(16) float Xs[2][32][68];
    int z = blockIdx.z;
    int i0 = blockIdx.x * 32, j0 = blockIdx.y * 64;
    int tid = threadIdx.x;
    int ti = tid >> 4, tj = tid & 15;
    int tr = tid >> 5, tc = tid & 31;
    int rr = tid >> 6, cc = tid & 63;
    float acc[2][4] = {};
    int nk = (z < 4) ? 16 : 4;
    float ur[4], xr[8];

    auto load_regs = [&](int kt) {
        if (z < 4) {
            int m0 = z * 512 + kt * 32;
            #pragma unroll
            for (int r = 0; r < 4; r++)
                ur[r] = g_U[(size_t)(i0 + tr + 8*r) * Mdim + m0 + tc];
            #pragma unroll
            for (int r = 0; r < 8; r++)
                xr[r] = x[(size_t)(j0 + tr + 8*r) * Mdim + m0 + tc];
        } else {
            int p0 = kt * 32;
            #pragma unroll
            for (int r = 0; r < 4; r++)
                ur[r] = g_DtD[(i0 + tr + 8*r) * Ldim + p0 + tc];
            #pragma unroll
            for (int r = 0; r < 8; r++)
                xr[r] = g_A[(p0 + rr + 4*r) * Ddim + j0 + cc];
        }
    };
    auto store_smem = [&](int b) {
        #pragma unroll
        for (int r = 0; r < 4; r++) Us[b][tc][tr + 8*r] = ur[r];
        if (z < 4) {
            #pragma unroll
            for (int r = 0; r < 8; r++) Xs[b][tc][tr + 8*r] = xr[r];
        } else {
            #pragma unroll
            for (int r = 0; r < 8; r++) Xs[b][rr + 4*r][cc] = xr[r];
        }
    };

    load_regs(0);
    store_smem(0);
    __syncthreads();
    for (int kt = 0; kt < nk; kt++) {
        int b = kt & 1;
        if (kt + 1 < nk) load_regs(kt + 1);
        float2 av = *(const float2*)&Us[b][0][2*ti];
        float4 bv = *(const float4*)&Xs[b][0][4*tj];
        #pragma unroll
        for (int kk = 0; kk < 32; kk++) {
            float2 av2; float4 bv2;
            if (kk < 31) {
                av2 = *(const float2*)&Us[b][kk+1][2*ti];
                bv2 = *(const float4*)&Xs[b][kk+1][4*tj];
            }
            acc[0][0] += av.x*bv.x; acc[0][1] += av.x*bv.y; acc[0][2] += av.x*bv.z; acc[0][3] += av.x*bv.w;
            acc[1][0] += av.y*bv.x; acc[1][1] += av.y*bv.y; acc[1][2] += av.y*bv.z; acc[1][3] += av.y*bv.w;
            if (kk < 31) { av = av2; bv = bv2; }
        }
        if (kt + 1 < nk) {
            store_smem((kt + 1) & 1);
            __syncthreads();
        }
    }
    float sc = (z == 4) ? 0.1f : 1.0f;
    int i = i0 + 2*ti, j = j0 + 4*tj;
    float* outp = &g_G[z][0];
    #pragma unroll
    for (int r = 0; r < 2; r++)
        #pragma unroll
        for (int c = 0; c < 4; c++)
            outp[(i + r) * Ddim + j + c] = acc[r][c] * sc;
}

// ---------- prox + momentum ----------
__global__ void k_update(float coeff) {
    if (g_done) return;
    float tau = g_scal[2], thr = g_scal[3];
    int idx = blockIdx.x * blockDim.x + threadIdx.x;
    float g = g_G[0][idx] + g_G[1][idx] + g_G[2][idx] + g_G[3][idx] + g_G[4][idx];
    float aold = g_A[idx], b = g_Bm[idx];
    float zv = b - tau * g;
    float az = fabsf(zv) - thr;
    float anew = (az > 0.f) ? copysignf(az, zv) : 0.f;
    g_A[idx]  = anew;
    g_Bm[idx] = aold + coeff * (anew - aold);
}

// ---------- forward: T = A@x, U = mask*(T - py) ----------
__global__ void __launch_bounds__(256) gemm_fwd(const float* __restrict__ x,
                                                const float* __restrict__ py,
                                                const float* __restrict__ mask) {
    if (g_done) return;
    __shared__ __align__(16) float As[2][32][34];
    __shared__ __align__(16) float Xs[2][32][68];
    int i0 = blockIdx.x * 32, m0 = blockIdx.y * 64;
    int tid = threadIdx.x;
    int ti = tid >> 4, tj = tid & 15;
    int tr = tid >> 5, tc = tid & 31;
    int rr = tid >> 6, cc = tid & 63;
    float acc[2][4] = {};
    float ar[4], xr[8];

    auto load_regs = [&](int kt) {
        int k0 = kt * 32;
        #pragma unroll
        for (int r = 0; r < 4; r++)
            ar[r] = g_A[(i0 + tr + 8*r) * Ddim + k0 + tc];
        #pragma unroll
        for (int r = 0; r < 8; r++)
            xr[r] = x[(size_t)(k0 + rr + 4*r) * Mdim + m0 + cc];
    };
    auto store_smem = [&](int b) {
        #pragma unroll
        for (int r = 0; r < 4; r++) As[b][tc][tr + 8*r] = ar[r];
        #pragma unroll
        for (int r = 0; r < 8; r++) Xs[b][rr + 4*r][cc] = xr[r];
    };

    load_regs(0);
    store_smem(0);
    __syncthreads();
    for (int kt = 0; kt < 16; kt++) {
        int b = kt & 1;
        if (kt + 1 < 16) load_regs(kt + 1);
        float2 av = *(const float2*)&As[b][0][2*ti];
        float4 bv = *(const float4*)&Xs[b][0][4*tj];
        #pragma unroll
        for (int kk = 0; kk < 32; kk++) {
            float2 av2; float4 bv2;
            if (kk < 31) {
                av2 = *(const float2*)&As[b][kk+1][2*ti];
                bv2 = *(const float4*)&Xs[b][kk+1][4*tj];
            }
            acc[0][0] += av.x*bv.x; acc[0][1] += av.x*bv.y; acc[0][2] += av.x*bv.z; acc[0][3] += av.x*bv.w;
            acc[1][0] += av.y*bv.x; acc[1][1] += av.y*bv.y; acc[1][2] += av.y*bv.z; acc[1][3] += av.y*bv.w;
            if (kk < 31) { av = av2; bv = bv2; }
        }
        if (kt + 1 < 16) {
            store_smem((kt + 1) & 1);
            __syncthreads();
        }
    }
    #pragma unroll
    for (int r = 0; r < 2; r++) {
        int i = i0 + 2*ti + r;
        #pragma unroll
        for (int c = 0; c < 4; c++) {
            int m = m0 + 4*tj + c;
            size_t o = (size_t)i * Mdim + m;
            float t = acc[r][c];
            g_T[o] = t;
            g_U[o] = mask[o] * (t - py[o]);
        }
    }
}

// ---------- convergence on Hankel tail (1024 threads, 8-way per diagonal) ----------
__global__ void k_conv() {
    if (g_done) return;
    __shared__ float diag[128];
    __shared__ float r1[128], r2[128];
    int tid = threadIdx.x;           // 1024 threads
    int t = tid >> 3, s = tid & 7;   // t: diagonal 0..127, s: chunk 0..7
    float sum = 0.f;
    if (t < NTAIL) {
        for (int i = t + 1 + s; i < Ldim; i += 8)
            sum += g_T[i * Mdim + (Mdim + t - i)];
    }
    sum += __shfl_down_sync(0xffffffff, sum, 4, 8);
    sum += __shfl_down_sync(0xffffffff, sum, 2, 8);
    sum += __shfl_down_sync(0xffffffff, sum, 1, 8);
    if (s == 0 && t < 128) diag[t] = (t < NTAIL) ? sum / (float)(NTAIL - t) : 0.f;
    __syncthreads();
    if (tid < 128) {
        float a = (tid < NTAIL) ? diag[tid] : 0.f;
        float y = (tid < NTAIL) ? g_ytail[tid] : 0.f;
        float d = y - a;
        r1[tid] = d * d;
        r2[tid] = y * y;
    }
    __syncthreads();
    for (int off = 64; off > 0; off >>= 1) {
        if (tid < off) { r1[tid] += r1[tid + off]; r2[tid] += r2[tid + off]; }
        __syncthreads();
    }
    if (tid == 0 && sqrtf(r1[0] / r2[0]) <= 1e-5f) g_done = 1;
    if (tid < NTAIL) g_ytail[tid] = diag[tid];
}

// ---------- output: (A@x, A) ----------
__global__ void k_output(float* __restrict__ out, int out_size) {
    int idx = blockIdx.x * blockDim.x + threadIdx.x;
    if (idx >= out_size) return;
    if (idx < Ldim*Mdim) out[idx] = g_T[idx];
    else if (idx < Ldim*Mdim + Ldim*Ddim) out[idx] = g_A[idx - Ldim*Mdim];
}

extern "C" void kernel_launch(void* const* d_in, const int* in_sizes, int n_in,
                              void* d_out, int out_size) {
    const float* x    = (const float*)d_in[0];
    const float* py   = (const float*)d_in[1];
    const float* mask = (const float*)d_in[2];
    const float* y0   = (const float*)d_in[3];
    float* outp = (float*)d_out;

    void *pS, *pP0, *pP1, *pDtD, *pQ0, *pQ1;
    cudaGetSymbolAddress(&pS,   g_S);
    cudaGetSymbolAddress(&pP0,  g_P0);
    cudaGetSymbolAddress(&pP1,  g_P1);
    cudaGetSymbolAddress(&pDtD, g_DtD);
    cudaGetSymbolAddress(&pQ0,  g_Q0);
    cudaGetSymbolAddress(&pQ1,  g_Q1);

    k_init<<<(Ldim*Mdim + 255)/256, 256>>>(mask, py, y0);
    k_delta<<<(Ldim*Ldim + 255)/256, 256>>>();
    k_dtd<<<(Ldim*Ldim + 255)/256, 256>>>();

    // maxeig(x x^T): 10 squarings + Rayleigh
    gemm_nt<<<dim3(16,16), 256>>>(x, x, (float*)pS, Ddim, Mdim);
    k_trace<<<1, 512>>>((const float*)pS, Ddim);
    k_normmat<<<(Ddim*Ddim + 255)/256, 256>>>((const float*)pS, (float*)pP0, Ddim*Ddim);
    for (int i = 0; i < 10; i++) {
        gemm_nt<<<dim3(16,16), 256>>>((const float*)pP0, (const float*)pP0, (float*)pP1, Ddim, Ddim);
        k_trace<<<1, 512>>>((const float*)pP1, Ddim);
        k_normmat<<<(Ddim*Ddim + 255)/256, 256>>>((const float*)pP1, (float*)pP0, Ddim*Ddim);
    }
    k_rayleigh<<<1, Ddim>>>((const float*)pP0, (const float*)pS, Ddim, 0);

    // maxeig(DtD): 17 squarings + Rayleigh
    k_trace<<<1, 512>>>((const float*)pDtD, Ldim);
    k_normmat<<<(Ldim*Ldim + 255)/256, 256>>>((const float*)pDtD, (float*)pQ0, Ldim*Ldim);
    for (int i = 0; i < 17; i++) {
        gemm_nt<<<dim3(4,4), 256>>>((const float*)pQ0, (const float*)pQ0, (float*)pQ1, Ldim, Ldim);
        k_trace<<<1, 512>>>((const float*)pQ1, Ldim);
        k_normmat<<<(Ldim*Ldim + 255)/256, 256>>>((const float*)pQ1, (float*)pQ0, Ldim*Ldim);
    }
    k_rayleigh<<<1, Ldim>>>((const float*)pQ0, (const float*)pDtD, Ldim, 1);

    k_scalars<<<1, 1>>>();

    float a = 1.0f;
    for (int it = 0; it < 200; it++) {
        float anew = (1.0f + sqrtf(1.0f + 4.0f * a * a)) * 0.5f;
        float coeff = (a - 1.0f) / anew;
        a = anew;
        gemm_grad<<<dim3(Ldim/32, Ddim/64, 5), 256>>>(x);
        k_update<<<(Ldim*Ddim)/256, 256>>>(coeff);
        gemm_fwd<<<dim3(Ldim/32, Mdim/64), 256>>>(x, py, mask);
        k_conv<<<1, 1024>>>();
    }

    k_output<<<(out_size + 255)/256, 256>>>(outp, out_size);
}